// round 2
// baseline (speedup 1.0000x reference)
#include <cuda_runtime.h>

#define MAX_NODES 100000
#define MAX_EDGES 1600000
#define OUTF 64
#define INF  128

// Scratch (no cudaMalloc allowed): ping-pong feature buffers + unpacked indices.
__device__ float g_bufA[MAX_NODES * OUTF];
__device__ float g_bufB[MAX_NODES * OUTF];
__device__ int   g_src[MAX_EDGES];
__device__ int   g_dst[MAX_EDGES];

// ---------------------------------------------------------------------------
// Unpack edge_index into int32 src/dst, auto-detecting int32 vs int64 storage.
// int64 little-endian with values in [0, 1e5): every high word is 0.
// Check 32 high-word positions; random int32 data fails this with p ~ 1e-160.
// ---------------------------------------------------------------------------
__global__ void extract_idx_kernel(const int* __restrict__ raw, int E,
                                   int* __restrict__ s_out,
                                   int* __restrict__ d_out_)
{
    bool is64 = true;
#pragma unroll
    for (int i = 1; i < 64; i += 2)
        if (raw[i] != 0) is64 = false;

    int e = blockIdx.x * blockDim.x + threadIdx.x;
    if (e >= E) return;
    if (is64) {
        s_out[e]  = raw[2 * e];
        d_out_[e] = raw[2 * E + 2 * e];
    } else {
        s_out[e]  = raw[e];
        d_out_[e] = raw[E + e];
    }
}

// ---------------------------------------------------------------------------
// GEMM: out[n][c] = sum_k x[n][k] * W[c][k] + bias[c]
// 64-node x 64-col tile per block, 256 threads, 4x4 register tile per thread.
// ---------------------------------------------------------------------------
__global__ void gemm_kernel(const float* __restrict__ x,
                            const float* __restrict__ W,
                            const float* __restrict__ bias,
                            float* __restrict__ out, int n)
{
    extern __shared__ float sm[];
    float* xs = sm;              // 64*128 floats
    float* ws = sm + 64 * INF;   // 128*65 floats (padded)

    const int tid = threadIdx.x;
    const int n_base = blockIdx.x * 64;

    // W transposed into smem: ws[k][c] = W[c*128 + k]
    for (int i = tid; i < OUTF * INF; i += 256) {
        int c = i >> 7;
        int k = i & 127;
        ws[k * 65 + c] = W[i];
    }
    // x tile (float4, coalesced), zero-pad out-of-range nodes
    for (int i = tid * 4; i < 64 * INF; i += 256 * 4) {
        int gn = n_base + (i >> 7);
        float4 v = make_float4(0.f, 0.f, 0.f, 0.f);
        if (gn < n) v = *(const float4*)(x + (size_t)gn * INF + (i & 127));
        *(float4*)(xs + i) = v;
    }
    __syncthreads();

    const int c0 = (tid & 15) * 4;
    const int n0 = (tid >> 4) * 4;

    float acc[4][4];
#pragma unroll
    for (int i = 0; i < 4; i++)
#pragma unroll
        for (int j = 0; j < 4; j++) acc[i][j] = 0.f;

#pragma unroll 4
    for (int k = 0; k < INF; k++) {
        float wv[4], xv[4];
#pragma unroll
        for (int j = 0; j < 4; j++) wv[j] = ws[k * 65 + c0 + j];
#pragma unroll
        for (int i = 0; i < 4; i++) xv[i] = xs[(n0 + i) * INF + k];
#pragma unroll
        for (int i = 0; i < 4; i++)
#pragma unroll
            for (int j = 0; j < 4; j++)
                acc[i][j] = fmaf(xv[i], wv[j], acc[i][j]);
    }

    float b0 = bias[c0], b1 = bias[c0 + 1], b2 = bias[c0 + 2], b3 = bias[c0 + 3];
#pragma unroll
    for (int i = 0; i < 4; i++) {
        int gn = n_base + n0 + i;
        if (gn < n) {
            float4 r;
            r.x = acc[i][0] + b0;
            r.y = acc[i][1] + b1;
            r.z = acc[i][2] + b2;
            r.w = acc[i][3] + b3;
            *(float4*)(out + (size_t)gn * OUTF + c0) = r;
        }
    }
}

// ---------------------------------------------------------------------------
// SpMM hop: hout[dst[e]] += w[e] * hin[src[e]], feature width 64.
// 16 threads per edge, one float4 each. Same-address index loads broadcast in L1.
// Scatter via red.global.add.v4.f32 (sm_90+ vector reduction, no return).
// ---------------------------------------------------------------------------
__global__ void spmm_kernel(const int* __restrict__ src,
                            const int* __restrict__ dst,
                            const float* __restrict__ w,
                            const float* __restrict__ hin,
                            float* __restrict__ hout, int E)
{
    int t = blockIdx.x * blockDim.x + threadIdx.x;
    int e = t >> 4;
    if (e >= E) return;

    int s  = src[e];
    int d  = dst[e];
    float ww = w[e];

    int q4 = (threadIdx.x & 15) * 4;   // column offset within the 64-wide row
    float4 v = *(const float4*)(hin + (size_t)s * OUTF + q4);
    v.x *= ww; v.y *= ww; v.z *= ww; v.w *= ww;

    float* po = hout + (size_t)d * OUTF + q4;
    asm volatile("red.global.add.v4.f32 [%0], {%1, %2, %3, %4};"
                 :: "l"(po), "f"(v.x), "f"(v.y), "f"(v.z), "f"(v.w)
                 : "memory");
}

// ---------------------------------------------------------------------------
extern "C" void kernel_launch(void* const* d_in, const int* in_sizes, int n_in,
                              void* d_out, int out_size)
{
    const float* x  = (const float*)d_in[0];
    const int*   ei = (const int*)d_in[1];       // [2, E], int32 or int64 (detected)
    const float* ew = (const float*)d_in[2];
    const float* Ww = (const float*)d_in[3];     // [64, 128]
    const float* Wb = (const float*)d_in[4];     // [64]
    float* out = (float*)d_out;

    int n = in_sizes[0] / INF;     // 100000
    int E = in_sizes[2];           // 1600000

    float *pA, *pB;
    int *pS, *pD;
    cudaGetSymbolAddress((void**)&pA, g_bufA);
    cudaGetSymbolAddress((void**)&pB, g_bufB);
    cudaGetSymbolAddress((void**)&pS, g_src);
    cudaGetSymbolAddress((void**)&pD, g_dst);

    const int GEMM_SMEM = (64 * INF + INF * 65) * (int)sizeof(float);  // 66048 B
    cudaFuncSetAttribute(gemm_kernel, cudaFuncAttributeMaxDynamicSharedMemorySize,
                         GEMM_SMEM);

    size_t hb = (size_t)n * OUTF * sizeof(float);

    // Unpack indices (also dtype-detects)
    extract_idx_kernel<<<(E + 255) / 256, 256>>>(ei, E, pS, pD);

    // h0 = x @ W^T + b
    gemm_kernel<<<(n + 63) / 64, 256, GEMM_SMEM>>>(x, Ww, Wb, pA, n);

    int spmm_blocks = (E * 16 + 255) / 256;

    // hop 1: A -> B
    cudaMemsetAsync(pB, 0, hb);
    spmm_kernel<<<spmm_blocks, 256>>>(pS, pD, ew, pA, pB, E);
    // hop 2: B -> A
    cudaMemsetAsync(pA, 0, hb);
    spmm_kernel<<<spmm_blocks, 256>>>(pS, pD, ew, pB, pA, E);
    // hop 3: A -> out
    cudaMemsetAsync(out, 0, hb);
    spmm_kernel<<<spmm_blocks, 256>>>(pS, pD, ew, pA, out, E);
}

// round 3
// speedup vs baseline: 1.2814x; 1.2814x over previous
#include <cuda_runtime.h>

#define MAX_NODES 100000
#define MAX_EDGES 1600000
#define OUTF 64
#define INF  128

// Scratch (no cudaMalloc allowed)
__device__ float g_bufA[MAX_NODES * OUTF];
__device__ float g_bufB[MAX_NODES * OUTF];
__device__ int   g_src[MAX_EDGES];
__device__ int   g_dst[MAX_EDGES];
__device__ int   g_deg[MAX_NODES];
__device__ int   g_row_ptr[MAX_NODES + 1];
__device__ int   g_wptr[MAX_NODES];
__device__ int2  g_csr[MAX_EDGES];      // {src, float_bits(w)} in dst-CSR order

// ---------------------------------------------------------------------------
// Unpack edge_index (auto int32/int64) AND count per-dst degrees.
// int64 little-endian with values < 2^31: all high words are zero.
// ---------------------------------------------------------------------------
__global__ void extract_count_kernel(const int* __restrict__ raw, int E,
                                     int* __restrict__ s_out,
                                     int* __restrict__ d_out_,
                                     int* __restrict__ deg)
{
    bool is64 = true;
#pragma unroll
    for (int i = 1; i < 64; i += 2)
        if (raw[i] != 0) is64 = false;

    int e = blockIdx.x * blockDim.x + threadIdx.x;
    if (e >= E) return;
    int s, d;
    if (is64) { s = raw[2 * e]; d = raw[2 * E + 2 * e]; }
    else      { s = raw[e];     d = raw[E + e]; }
    s_out[e] = s;
    d_out_[e] = d;
    atomicAdd(&deg[d], 1);
}

// ---------------------------------------------------------------------------
// Exclusive scan of deg[0..n) -> row_ptr[0..n], wptr copy. Single block,
// 1024 threads, 4 elements/thread (4096/chunk), warp-shuffle scans.
// ---------------------------------------------------------------------------
__global__ void scan_kernel(const int* __restrict__ deg,
                            int* __restrict__ row_ptr,
                            int* __restrict__ wptr, int n)
{
    __shared__ int warp_sums[32];
    __shared__ int carry_s;
    if (threadIdx.x == 0) carry_s = 0;
    __syncthreads();

    const int lane = threadIdx.x & 31;
    const int wid  = threadIdx.x >> 5;

    for (int base = 0; base < n; base += 4096) {
        int idx = base + threadIdx.x * 4;
        int v[4];
#pragma unroll
        for (int j = 0; j < 4; j++) v[j] = (idx + j < n) ? deg[idx + j] : 0;
        int local = v[0] + v[1] + v[2] + v[3];

        // inclusive warp scan of per-thread sums
        int s = local;
#pragma unroll
        for (int off = 1; off < 32; off <<= 1) {
            int t = __shfl_up_sync(0xffffffffu, s, off);
            if (lane >= off) s += t;
        }
        if (lane == 31) warp_sums[wid] = s;
        __syncthreads();
        if (wid == 0) {
            int ws = warp_sums[lane];
#pragma unroll
            for (int off = 1; off < 32; off <<= 1) {
                int t = __shfl_up_sync(0xffffffffu, ws, off);
                if (lane >= off) ws += t;
            }
            warp_sums[lane] = ws;  // inclusive across warps
        }
        __syncthreads();

        int carry = carry_s;
        int warp_excl = (wid == 0) ? 0 : warp_sums[wid - 1];
        int run = carry + warp_excl + (s - local);   // exclusive prefix of elem 0
#pragma unroll
        for (int j = 0; j < 4; j++) {
            int i = idx + j;
            if (i < n) { row_ptr[i] = run; wptr[i] = run; }
            run += v[j];
        }
        int chunk_total = warp_sums[31];
        __syncthreads();
        if (threadIdx.x == 0) carry_s = carry + chunk_total;
        __syncthreads();
    }
    if (threadIdx.x == 0) row_ptr[n] = carry_s;
}

// ---------------------------------------------------------------------------
// Scatter edges into CSR slots (order within a row is nondeterministic; only
// affects fp addition order, far below tolerance).
// ---------------------------------------------------------------------------
__global__ void scatter_kernel(const int* __restrict__ src,
                               const int* __restrict__ dst,
                               const float* __restrict__ w,
                               int* __restrict__ wptr,
                               int2* __restrict__ csr, int E)
{
    int e = blockIdx.x * blockDim.x + threadIdx.x;
    if (e >= E) return;
    int pos = atomicAdd(&wptr[dst[e]], 1);
    csr[pos] = make_int2(src[e], __float_as_int(w[e]));
}

// ---------------------------------------------------------------------------
// GEMM: out[n][c] = sum_k x[n][k] * W[c][k] + bias[c]
// ---------------------------------------------------------------------------
__global__ void gemm_kernel(const float* __restrict__ x,
                            const float* __restrict__ W,
                            const float* __restrict__ bias,
                            float* __restrict__ out, int n)
{
    extern __shared__ float sm[];
    float* xs = sm;              // 64*128
    float* ws = sm + 64 * INF;   // 128*65 padded

    const int tid = threadIdx.x;
    const int n_base = blockIdx.x * 64;

    for (int i = tid; i < OUTF * INF; i += 256) {
        int c = i >> 7;
        int k = i & 127;
        ws[k * 65 + c] = W[i];
    }
    for (int i = tid * 4; i < 64 * INF; i += 256 * 4) {
        int gn = n_base + (i >> 7);
        float4 v = make_float4(0.f, 0.f, 0.f, 0.f);
        if (gn < n) v = *(const float4*)(x + (size_t)gn * INF + (i & 127));
        *(float4*)(xs + i) = v;
    }
    __syncthreads();

    const int c0 = (tid & 15) * 4;
    const int n0 = (tid >> 4) * 4;

    float acc[4][4];
#pragma unroll
    for (int i = 0; i < 4; i++)
#pragma unroll
        for (int j = 0; j < 4; j++) acc[i][j] = 0.f;

#pragma unroll 4
    for (int k = 0; k < INF; k++) {
        float wv[4], xv[4];
#pragma unroll
        for (int j = 0; j < 4; j++) wv[j] = ws[k * 65 + c0 + j];
#pragma unroll
        for (int i = 0; i < 4; i++) xv[i] = xs[(n0 + i) * INF + k];
#pragma unroll
        for (int i = 0; i < 4; i++)
#pragma unroll
            for (int j = 0; j < 4; j++)
                acc[i][j] = fmaf(xv[i], wv[j], acc[i][j]);
    }

    float b0 = bias[c0], b1 = bias[c0 + 1], b2 = bias[c0 + 2], b3 = bias[c0 + 3];
#pragma unroll
    for (int i = 0; i < 4; i++) {
        int gn = n_base + n0 + i;
        if (gn < n) {
            float4 r;
            r.x = acc[i][0] + b0;
            r.y = acc[i][1] + b1;
            r.z = acc[i][2] + b2;
            r.w = acc[i][3] + b3;
            *(float4*)(out + (size_t)gn * OUTF + c0) = r;
        }
    }
}

// ---------------------------------------------------------------------------
// CSR SpMM hop: hout[v] = sum_{i in row v} w_i * hin[src_i].
// 16 threads per node row, one float4 lane each. No atomics, no pre-zeroing.
// ---------------------------------------------------------------------------
__global__ void spmm_csr_kernel(const int* __restrict__ row_ptr,
                                const int2* __restrict__ csr,
                                const float* __restrict__ hin,
                                float* __restrict__ hout, int n)
{
    int t = blockIdx.x * blockDim.x + threadIdx.x;
    int v = t >> 4;
    if (v >= n) return;
    int q4 = (threadIdx.x & 15) * 4;

    int beg = __ldg(&row_ptr[v]);
    int end = __ldg(&row_ptr[v + 1]);

    float4 acc = make_float4(0.f, 0.f, 0.f, 0.f);
    for (int i = beg; i < end; i++) {
        int2 e = __ldg(&csr[i]);                 // broadcast across the 16 lanes
        float w = __int_as_float(e.y);
        float4 hv = *(const float4*)(hin + (size_t)e.x * OUTF + q4);
        acc.x = fmaf(w, hv.x, acc.x);
        acc.y = fmaf(w, hv.y, acc.y);
        acc.z = fmaf(w, hv.z, acc.z);
        acc.w = fmaf(w, hv.w, acc.w);
    }
    *(float4*)(hout + (size_t)v * OUTF + q4) = acc;
}

// ---------------------------------------------------------------------------
extern "C" void kernel_launch(void* const* d_in, const int* in_sizes, int n_in,
                              void* d_out, int out_size)
{
    const float* x  = (const float*)d_in[0];
    const int*   ei = (const int*)d_in[1];
    const float* ew = (const float*)d_in[2];
    const float* Ww = (const float*)d_in[3];
    const float* Wb = (const float*)d_in[4];
    float* out = (float*)d_out;

    int n = in_sizes[0] / INF;     // 100000
    int E = in_sizes[2];           // 1600000

    float *pA, *pB;
    int *pS, *pD, *pDeg, *pRow, *pW;
    int2 *pCsr;
    cudaGetSymbolAddress((void**)&pA, g_bufA);
    cudaGetSymbolAddress((void**)&pB, g_bufB);
    cudaGetSymbolAddress((void**)&pS, g_src);
    cudaGetSymbolAddress((void**)&pD, g_dst);
    cudaGetSymbolAddress((void**)&pDeg, g_deg);
    cudaGetSymbolAddress((void**)&pRow, g_row_ptr);
    cudaGetSymbolAddress((void**)&pW, g_wptr);
    cudaGetSymbolAddress((void**)&pCsr, g_csr);

    const int GEMM_SMEM = (64 * INF + INF * 65) * (int)sizeof(float);
    cudaFuncSetAttribute(gemm_kernel, cudaFuncAttributeMaxDynamicSharedMemorySize,
                         GEMM_SMEM);

    // ---- CSR build ----
    cudaMemsetAsync(pDeg, 0, (size_t)n * sizeof(int));
    extract_count_kernel<<<(E + 255) / 256, 256>>>(ei, E, pS, pD, pDeg);
    scan_kernel<<<1, 1024>>>(pDeg, pRow, pW, n);
    scatter_kernel<<<(E + 255) / 256, 256>>>(pS, pD, ew, pW, pCsr, E);

    // ---- h0 = x @ W^T + b (overlaps with CSR build on the same stream order) ----
    gemm_kernel<<<(n + 63) / 64, 256, GEMM_SMEM>>>(x, Ww, Wb, pA, n);

    // ---- 3 propagation hops, no atomics ----
    int hop_blocks = (n * 16 + 255) / 256;
    spmm_csr_kernel<<<hop_blocks, 256>>>(pRow, pCsr, pA, pB, n);
    spmm_csr_kernel<<<hop_blocks, 256>>>(pRow, pCsr, pB, pA, n);
    spmm_csr_kernel<<<hop_blocks, 256>>>(pRow, pCsr, pA, out, n);
}

// round 4
// speedup vs baseline: 1.6073x; 1.2543x over previous
#include <cuda_runtime.h>

#define MAX_NODES 100000
#define MAX_EDGES 1600000
#define OUTF 64
#define INF  128
#define WS_STRIDE 68   // padded W row stride (floats): 16B-aligned, bank-spread

// Scratch (no cudaMalloc allowed)
__device__ float g_bufA[MAX_NODES * OUTF];
__device__ float g_bufB[MAX_NODES * OUTF];
__device__ int   g_src[MAX_EDGES];
__device__ int   g_dst[MAX_EDGES];
__device__ int   g_deg[MAX_NODES];
__device__ int   g_row_ptr[MAX_NODES + 1];
__device__ int   g_wptr[MAX_NODES];
__device__ int   g_blk[1024];           // per-block sums for the scan
__device__ int2  g_csr[MAX_EDGES];      // {src, float_bits(w)} dst-CSR order

// ---------------- packed f32x2 helpers (Blackwell FFMA2) --------------------
__device__ __forceinline__ unsigned long long pk2(float lo, float hi) {
    unsigned long long r;
    asm("mov.b64 %0, {%1,%2};" : "=l"(r) : "f"(lo), "f"(hi));
    return r;
}
__device__ __forceinline__ void upk2(float& lo, float& hi, unsigned long long v) {
    asm("mov.b64 {%0,%1}, %2;" : "=f"(lo), "=f"(hi) : "l"(v));
}
__device__ __forceinline__ void fma2(unsigned long long& d,
                                     unsigned long long a, unsigned long long b) {
    asm("fma.rn.f32x2 %0, %1, %2, %0;" : "+l"(d) : "l"(a), "l"(b));
}

// ---------------------------------------------------------------------------
// Unpack edge_index (auto int32/int64) AND count per-dst degrees.
// ---------------------------------------------------------------------------
__global__ void extract_count_kernel(const int* __restrict__ raw, int E,
                                     int* __restrict__ s_out,
                                     int* __restrict__ d_out_,
                                     int* __restrict__ deg)
{
    bool is64 = true;
#pragma unroll
    for (int i = 1; i < 64; i += 2)
        if (raw[i] != 0) is64 = false;

    int e = blockIdx.x * blockDim.x + threadIdx.x;
    if (e >= E) return;
    int s, d;
    if (is64) { s = raw[2 * e]; d = raw[2 * E + 2 * e]; }
    else      { s = raw[e];     d = raw[E + e]; }
    s_out[e] = s;
    d_out_[e] = d;
    atomicAdd(&deg[d], 1);
}

// ---------------- 3-phase exclusive scan of deg -> row_ptr/wptr -------------
__global__ void scan1_kernel(const int* __restrict__ deg,
                             int* __restrict__ blk, int n)
{
    __shared__ int wsum[8];
    int i = blockIdx.x * 256 + threadIdx.x;
    int v = (i < n) ? deg[i] : 0;
    int lane = threadIdx.x & 31, wid = threadIdx.x >> 5;
    int s = v;
#pragma unroll
    for (int o = 1; o < 32; o <<= 1) s += __shfl_xor_sync(0xffffffffu, s, o);
    if (lane == 0) wsum[wid] = s;
    __syncthreads();
    if (threadIdx.x == 0) {
        int t = 0;
#pragma unroll
        for (int j = 0; j < 8; j++) t += wsum[j];
        blk[blockIdx.x] = t;
    }
}

__global__ void scan2_kernel(int* __restrict__ blk, int nb)
{
    // single block, 1024 threads: exclusive scan of blk[0..nb) in place
    __shared__ int wsum[32];
    int lane = threadIdx.x & 31, wid = threadIdx.x >> 5;
    int v = (threadIdx.x < nb) ? blk[threadIdx.x] : 0;
    int s = v;
#pragma unroll
    for (int o = 1; o < 32; o <<= 1) {
        int t = __shfl_up_sync(0xffffffffu, s, o);
        if (lane >= o) s += t;
    }
    if (lane == 31) wsum[wid] = s;
    __syncthreads();
    if (wid == 0) {
        int ws = wsum[lane];
#pragma unroll
        for (int o = 1; o < 32; o <<= 1) {
            int t = __shfl_up_sync(0xffffffffu, ws, o);
            if (lane >= o) ws += t;
        }
        wsum[lane] = ws;
    }
    __syncthreads();
    int excl = s - v + (wid ? wsum[wid - 1] : 0);
    if (threadIdx.x < nb) blk[threadIdx.x] = excl;
}

__global__ void scan3_kernel(const int* __restrict__ deg,
                             const int* __restrict__ blk,
                             int* __restrict__ row_ptr,
                             int* __restrict__ wptr, int n, int E)
{
    __shared__ int wsum[8];
    int i = blockIdx.x * 256 + threadIdx.x;
    int v = (i < n) ? deg[i] : 0;
    int lane = threadIdx.x & 31, wid = threadIdx.x >> 5;
    int s = v;
#pragma unroll
    for (int o = 1; o < 32; o <<= 1) {
        int t = __shfl_up_sync(0xffffffffu, s, o);
        if (lane >= o) s += t;
    }
    if (lane == 31) wsum[wid] = s;
    __syncthreads();
    if (wid == 0 && lane < 8) {
        int ws = wsum[lane];
#pragma unroll
        for (int o = 1; o < 8; o <<= 1) {
            int t = __shfl_up_sync(0x000000ffu, ws, o);
            if (lane >= o) ws += t;
        }
        wsum[lane] = ws;
    }
    __syncthreads();
    int excl = s - v + (wid ? wsum[wid - 1] : 0) + blk[blockIdx.x];
    if (i < n) { row_ptr[i] = excl; wptr[i] = excl; }
    if (i == 0) row_ptr[n] = E;
}

// ---------------------------------------------------------------------------
__global__ void scatter_kernel(const int* __restrict__ src,
                               const int* __restrict__ dst,
                               const float* __restrict__ w,
                               int* __restrict__ wptr,
                               int2* __restrict__ csr, int E)
{
    int e = blockIdx.x * blockDim.x + threadIdx.x;
    if (e >= E) return;
    int pos = atomicAdd(&wptr[dst[e]], 1);
    csr[pos] = make_int2(src[e], __float_as_int(w[e]));
}

// ---------------------------------------------------------------------------
// GEMM with packed fma.rn.f32x2: out[n][c] = sum_k x[n][k]*W[c][k] + bias[c]
// 64x64 tile / block, 256 threads, each thread: 4 nodes x 4 cols (2 f32x2 pairs)
// ---------------------------------------------------------------------------
__global__ void gemm_kernel(const float* __restrict__ x,
                            const float* __restrict__ W,
                            const float* __restrict__ bias,
                            float* __restrict__ out, int n)
{
    extern __shared__ float sm[];
    float* xs = sm;                    // 64*128
    float* ws = sm + 64 * INF;         // 128*WS_STRIDE

    const int tid = threadIdx.x;
    const int n_base = blockIdx.x * 64;

    // W transposed into smem: ws[k*WS_STRIDE + c] = W[c*128 + k]
    for (int i = tid; i < OUTF * INF; i += 256) {
        int c = i >> 7;
        int k = i & 127;
        ws[k * WS_STRIDE + c] = W[i];
    }
    // x tile (float4, coalesced), zero-pad out-of-range nodes
    for (int i = tid * 4; i < 64 * INF; i += 256 * 4) {
        int gn = n_base + (i >> 7);
        float4 v = make_float4(0.f, 0.f, 0.f, 0.f);
        if (gn < n) v = *(const float4*)(x + (size_t)gn * INF + (i & 127));
        *(float4*)(xs + i) = v;
    }
    __syncthreads();

    const int c0 = (tid & 15) * 4;
    const int n0 = (tid >> 4) * 4;

    unsigned long long acc[4][2];
#pragma unroll
    for (int i = 0; i < 4; i++) { acc[i][0] = 0ull; acc[i][1] = 0ull; }

#pragma unroll 4
    for (int k = 0; k < INF; k++) {
        float4 wv = *(const float4*)(ws + k * WS_STRIDE + c0);   // LDS.128
        unsigned long long w01 = pk2(wv.x, wv.y);
        unsigned long long w23 = pk2(wv.z, wv.w);
#pragma unroll
        for (int i = 0; i < 4; i++) {
            float xv = xs[(n0 + i) * INF + k];                   // broadcast LDS
            unsigned long long xx = pk2(xv, xv);
            fma2(acc[i][0], xx, w01);
            fma2(acc[i][1], xx, w23);
        }
    }

    float b0 = bias[c0], b1 = bias[c0 + 1], b2 = bias[c0 + 2], b3 = bias[c0 + 3];
#pragma unroll
    for (int i = 0; i < 4; i++) {
        int gn = n_base + n0 + i;
        if (gn < n) {
            float4 r;
            upk2(r.x, r.y, acc[i][0]);
            upk2(r.z, r.w, acc[i][1]);
            r.x += b0; r.y += b1; r.z += b2; r.w += b3;
            *(float4*)(out + (size_t)gn * OUTF + c0) = r;
        }
    }
}

// ---------------------------------------------------------------------------
// CSR SpMM hop: hout[v] = sum_i w_i * hin[src_i]. 8 lanes/node, 2 float4 each,
// edge loop unrolled by 2 for MLP (4 independent 16B loads in flight).
// ---------------------------------------------------------------------------
__global__ void spmm_csr_kernel(const int* __restrict__ row_ptr,
                                const int2* __restrict__ csr,
                                const float* __restrict__ hin,
                                float* __restrict__ hout, int n)
{
    int t = blockIdx.x * blockDim.x + threadIdx.x;
    int v = t >> 3;
    if (v >= n) return;
    int q8 = (threadIdx.x & 7) * 8;

    int beg = __ldg(&row_ptr[v]);
    int end = __ldg(&row_ptr[v + 1]);

    float4 a0 = make_float4(0.f, 0.f, 0.f, 0.f);
    float4 a1 = make_float4(0.f, 0.f, 0.f, 0.f);

    int i = beg;
    for (; i + 2 <= end; i += 2) {
        int2 e0 = __ldg(&csr[i]);
        int2 e1 = __ldg(&csr[i + 1]);
        const float4* p0 = (const float4*)(hin + (size_t)e0.x * OUTF + q8);
        const float4* p1 = (const float4*)(hin + (size_t)e1.x * OUTF + q8);
        float4 h00 = p0[0], h01 = p0[1];
        float4 h10 = p1[0], h11 = p1[1];
        float w0 = __int_as_float(e0.y);
        float w1 = __int_as_float(e1.y);
        a0.x = fmaf(w0, h00.x, a0.x); a0.y = fmaf(w0, h00.y, a0.y);
        a0.z = fmaf(w0, h00.z, a0.z); a0.w = fmaf(w0, h00.w, a0.w);
        a1.x = fmaf(w0, h01.x, a1.x); a1.y = fmaf(w0, h01.y, a1.y);
        a1.z = fmaf(w0, h01.z, a1.z); a1.w = fmaf(w0, h01.w, a1.w);
        a0.x = fmaf(w1, h10.x, a0.x); a0.y = fmaf(w1, h10.y, a0.y);
        a0.z = fmaf(w1, h10.z, a0.z); a0.w = fmaf(w1, h10.w, a0.w);
        a1.x = fmaf(w1, h11.x, a1.x); a1.y = fmaf(w1, h11.y, a1.y);
        a1.z = fmaf(w1, h11.z, a1.z); a1.w = fmaf(w1, h11.w, a1.w);
    }
    if (i < end) {
        int2 e0 = __ldg(&csr[i]);
        const float4* p0 = (const float4*)(hin + (size_t)e0.x * OUTF + q8);
        float4 h00 = p0[0], h01 = p0[1];
        float w0 = __int_as_float(e0.y);
        a0.x = fmaf(w0, h00.x, a0.x); a0.y = fmaf(w0, h00.y, a0.y);
        a0.z = fmaf(w0, h00.z, a0.z); a0.w = fmaf(w0, h00.w, a0.w);
        a1.x = fmaf(w0, h01.x, a1.x); a1.y = fmaf(w0, h01.y, a1.y);
        a1.z = fmaf(w0, h01.z, a1.z); a1.w = fmaf(w0, h01.w, a1.w);
    }

    float4* po = (float4*)(hout + (size_t)v * OUTF + q8);
    po[0] = a0;
    po[1] = a1;
}

// ---------------------------------------------------------------------------
extern "C" void kernel_launch(void* const* d_in, const int* in_sizes, int n_in,
                              void* d_out, int out_size)
{
    const float* x  = (const float*)d_in[0];
    const int*   ei = (const int*)d_in[1];
    const float* ew = (const float*)d_in[2];
    const float* Ww = (const float*)d_in[3];
    const float* Wb = (const float*)d_in[4];
    float* out = (float*)d_out;

    int n = in_sizes[0] / INF;     // 100000
    int E = in_sizes[2];           // 1600000

    float *pA, *pB;
    int *pS, *pD, *pDeg, *pRow, *pW, *pBlk;
    int2 *pCsr;
    cudaGetSymbolAddress((void**)&pA, g_bufA);
    cudaGetSymbolAddress((void**)&pB, g_bufB);
    cudaGetSymbolAddress((void**)&pS, g_src);
    cudaGetSymbolAddress((void**)&pD, g_dst);
    cudaGetSymbolAddress((void**)&pDeg, g_deg);
    cudaGetSymbolAddress((void**)&pRow, g_row_ptr);
    cudaGetSymbolAddress((void**)&pW, g_wptr);
    cudaGetSymbolAddress((void**)&pBlk, g_blk);
    cudaGetSymbolAddress((void**)&pCsr, g_csr);

    const int GEMM_SMEM = (64 * INF + INF * WS_STRIDE) * (int)sizeof(float);
    cudaFuncSetAttribute(gemm_kernel, cudaFuncAttributeMaxDynamicSharedMemorySize,
                         GEMM_SMEM);

    int nb = (n + 255) / 256;

    // ---- CSR build ----
    cudaMemsetAsync(pDeg, 0, (size_t)n * sizeof(int));
    extract_count_kernel<<<(E + 255) / 256, 256>>>(ei, E, pS, pD, pDeg);
    scan1_kernel<<<nb, 256>>>(pDeg, pBlk, n);
    scan2_kernel<<<1, 1024>>>(pBlk, nb);
    scan3_kernel<<<nb, 256>>>(pDeg, pBlk, pRow, pW, n, E);
    scatter_kernel<<<(E + 255) / 256, 256>>>(pS, pD, ew, pW, pCsr, E);

    // ---- h0 = x @ W^T + b ----
    gemm_kernel<<<(n + 63) / 64, 256, GEMM_SMEM>>>(x, Ww, Wb, pA, n);

    // ---- 3 propagation hops ----
    int hop_blocks = (n * 8 + 255) / 256;
    spmm_csr_kernel<<<hop_blocks, 256>>>(pRow, pCsr, pA, pB, n);
    spmm_csr_kernel<<<hop_blocks, 256>>>(pRow, pCsr, pB, pA, n);
    spmm_csr_kernel<<<hop_blocks, 256>>>(pRow, pCsr, pA, out, n);
}

// round 6
// speedup vs baseline: 1.8658x; 1.1608x over previous
#include <cuda_runtime.h>
#include <cuda_fp16.h>

#define MAX_NODES 100000
#define MAX_EDGES 1600000
#define OUTF 64
#define INF  128
#define XT_STRIDE 68   // padded strides (floats): 16B-aligned, bank-spread

// Scratch (no cudaMalloc allowed)
__device__ __half g_hA[MAX_NODES * OUTF];   // fp16 feature ping-pong
__device__ __half g_hB[MAX_NODES * OUTF];
__device__ int   g_src[MAX_EDGES];
__device__ int   g_dst[MAX_EDGES];
__device__ int   g_deg[MAX_NODES];
__device__ int   g_row_ptr[MAX_NODES + 1];
__device__ int   g_wptr[MAX_NODES];
__device__ int   g_blk[1024];
__device__ int2  g_csr[MAX_EDGES];          // {src, float_bits(w)} dst-CSR order

// ---------------- packed f32x2 helpers (Blackwell FFMA2) --------------------
__device__ __forceinline__ unsigned long long pk2(float lo, float hi) {
    unsigned long long r;
    asm("mov.b64 %0, {%1,%2};" : "=l"(r) : "f"(lo), "f"(hi));
    return r;
}
__device__ __forceinline__ void upk2(float& lo, float& hi, unsigned long long v) {
    asm("mov.b64 {%0,%1}, %2;" : "=f"(lo), "=f"(hi) : "l"(v));
}
__device__ __forceinline__ void fma2(unsigned long long& d,
                                     unsigned long long a, unsigned long long b) {
    asm("fma.rn.f32x2 %0, %1, %2, %0;" : "+l"(d) : "l"(a), "l"(b));
}

// ---------------------------------------------------------------------------
// Unpack edge_index (auto int32/int64) AND count per-dst degrees.
// ---------------------------------------------------------------------------
__global__ void extract_count_kernel(const int* __restrict__ raw, int E,
                                     int* __restrict__ s_out,
                                     int* __restrict__ d_out_,
                                     int* __restrict__ deg)
{
    bool is64 = true;
#pragma unroll
    for (int i = 1; i < 64; i += 2)
        if (raw[i] != 0) is64 = false;

    int e = blockIdx.x * blockDim.x + threadIdx.x;
    if (e >= E) return;
    int s, d;
    if (is64) { s = raw[2 * e]; d = raw[2 * E + 2 * e]; }
    else      { s = raw[e];     d = raw[E + e]; }
    s_out[e] = s;
    d_out_[e] = d;
    atomicAdd(&deg[d], 1);
}

// ---------------- 3-phase exclusive scan of deg -> row_ptr/wptr -------------
__global__ void scan1_kernel(const int* __restrict__ deg,
                             int* __restrict__ blk, int n)
{
    __shared__ int wsum[8];
    int i = blockIdx.x * 256 + threadIdx.x;
    int v = (i < n) ? deg[i] : 0;
    int lane = threadIdx.x & 31, wid = threadIdx.x >> 5;
    int s = v;
#pragma unroll
    for (int o = 1; o < 32; o <<= 1) s += __shfl_xor_sync(0xffffffffu, s, o);
    if (lane == 0) wsum[wid] = s;
    __syncthreads();
    if (threadIdx.x == 0) {
        int t = 0;
#pragma unroll
        for (int j = 0; j < 8; j++) t += wsum[j];
        blk[blockIdx.x] = t;
    }
}

__global__ void scan2_kernel(int* __restrict__ blk, int nb)
{
    __shared__ int wsum[32];
    int lane = threadIdx.x & 31, wid = threadIdx.x >> 5;
    int v = (threadIdx.x < nb) ? blk[threadIdx.x] : 0;
    int s = v;
#pragma unroll
    for (int o = 1; o < 32; o <<= 1) {
        int t = __shfl_up_sync(0xffffffffu, s, o);
        if (lane >= o) s += t;
    }
    if (lane == 31) wsum[wid] = s;
    __syncthreads();
    if (wid == 0) {
        int ws = wsum[lane];
#pragma unroll
        for (int o = 1; o < 32; o <<= 1) {
            int t = __shfl_up_sync(0xffffffffu, ws, o);
            if (lane >= o) ws += t;
        }
        wsum[lane] = ws;
    }
    __syncthreads();
    int excl = s - v + (wid ? wsum[wid - 1] : 0);
    if (threadIdx.x < nb) blk[threadIdx.x] = excl;
}

__global__ void scan3_kernel(const int* __restrict__ deg,
                             const int* __restrict__ blk,
                             int* __restrict__ row_ptr,
                             int* __restrict__ wptr, int n, int E)
{
    __shared__ int wsum[8];
    int i = blockIdx.x * 256 + threadIdx.x;
    int v = (i < n) ? deg[i] : 0;
    int lane = threadIdx.x & 31, wid = threadIdx.x >> 5;
    int s = v;
#pragma unroll
    for (int o = 1; o < 32; o <<= 1) {
        int t = __shfl_up_sync(0xffffffffu, s, o);
        if (lane >= o) s += t;
    }
    if (lane == 31) wsum[wid] = s;
    __syncthreads();
    if (wid == 0 && lane < 8) {
        int ws = wsum[lane];
#pragma unroll
        for (int o = 1; o < 8; o <<= 1) {
            int t = __shfl_up_sync(0x000000ffu, ws, o);
            if (lane >= o) ws += t;
        }
        wsum[lane] = ws;
    }
    __syncthreads();
    int excl = s - v + (wid ? wsum[wid - 1] : 0) + blk[blockIdx.x];
    if (i < n) { row_ptr[i] = excl; wptr[i] = excl; }
    if (i == 0) row_ptr[n] = E;
}

// ---------------------------------------------------------------------------
__global__ void scatter_kernel(const int* __restrict__ src,
                               const int* __restrict__ dst,
                               const float* __restrict__ w,
                               int* __restrict__ wptr,
                               int2* __restrict__ csr, int E)
{
    int e = blockIdx.x * blockDim.x + threadIdx.x;
    if (e >= E) return;
    int pos = atomicAdd(&wptr[dst[e]], 1);
    csr[pos] = make_int2(src[e], __float_as_int(w[e]));
}

// ---------------------------------------------------------------------------
// GEMM, node-packed f32x2: h0[n][c] = (sum_k x[n][k]*W[c][k] + bias[c]) as fp16
// 64x64 tile / block, 256 threads, thread = 2 node-pairs x 4 cols.
// ---------------------------------------------------------------------------
__global__ void gemm_kernel(const float* __restrict__ x,
                            const float* __restrict__ W,
                            const float* __restrict__ bias,
                            __half* __restrict__ out, int n)
{
    extern __shared__ float sm[];
    float* xsT = sm;                          // [128 k][XT_STRIDE] node-inner
    float* ws  = sm + INF * XT_STRIDE;        // [128 k][XT_STRIDE] col-inner

    const int tid = threadIdx.x;
    const int n_base = blockIdx.x * 64;

    // W transposed: ws[k*XT + c] = W[c*128 + k]
    for (int i = tid; i < OUTF * INF; i += 256) {
        int c = i >> 7;
        int k = i & 127;
        ws[k * XT_STRIDE + c] = W[i];
    }
    // x transposed into smem: xsT[k][node]
    {
        int node = tid & 63;
        int kb = (tid >> 6) * 32;
        int gn = n_base + node;
#pragma unroll
        for (int j = 0; j < 8; j++) {
            int k = kb + j * 4;
            float4 v = make_float4(0.f, 0.f, 0.f, 0.f);
            if (gn < n) v = *(const float4*)(x + (size_t)gn * INF + k);
            xsT[(k + 0) * XT_STRIDE + node] = v.x;
            xsT[(k + 1) * XT_STRIDE + node] = v.y;
            xsT[(k + 2) * XT_STRIDE + node] = v.z;
            xsT[(k + 3) * XT_STRIDE + node] = v.w;
        }
    }
    __syncthreads();

    const int c0 = (tid & 15) * 4;
    const int n0 = (tid >> 4) * 4;

    unsigned long long acc[2][4];
#pragma unroll
    for (int p = 0; p < 2; p++)
#pragma unroll
        for (int j = 0; j < 4; j++) acc[p][j] = 0ull;

#pragma unroll 4
    for (int k = 0; k < INF; k++) {
        ulonglong2 xp = *(const ulonglong2*)(xsT + k * XT_STRIDE + n0); // 2 pairs
        float4 wv = *(const float4*)(ws + k * XT_STRIDE + c0);
        unsigned long long w0 = pk2(wv.x, wv.x);
        unsigned long long w1 = pk2(wv.y, wv.y);
        unsigned long long w2 = pk2(wv.z, wv.z);
        unsigned long long w3 = pk2(wv.w, wv.w);
        fma2(acc[0][0], xp.x, w0); fma2(acc[0][1], xp.x, w1);
        fma2(acc[0][2], xp.x, w2); fma2(acc[0][3], xp.x, w3);
        fma2(acc[1][0], xp.y, w0); fma2(acc[1][1], xp.y, w1);
        fma2(acc[1][2], xp.y, w2); fma2(acc[1][3], xp.y, w3);
    }

    float b0 = bias[c0], b1 = bias[c0 + 1], b2 = bias[c0 + 2], b3 = bias[c0 + 3];
#pragma unroll
    for (int p = 0; p < 2; p++) {
        float lo[4], hi[4];
#pragma unroll
        for (int j = 0; j < 4; j++) upk2(lo[j], hi[j], acc[p][j]);
        int na = n_base + n0 + 2 * p;
        if (na < n) {
            __half2 h01 = __floats2half2_rn(lo[0] + b0, lo[1] + b1);
            __half2 h23 = __floats2half2_rn(lo[2] + b2, lo[3] + b3);
            *(__half2*)(out + (size_t)na * OUTF + c0)     = h01;
            *(__half2*)(out + (size_t)na * OUTF + c0 + 2) = h23;
        }
        int nb_ = na + 1;
        if (nb_ < n) {
            __half2 h01 = __floats2half2_rn(hi[0] + b0, hi[1] + b1);
            __half2 h23 = __floats2half2_rn(hi[2] + b2, hi[3] + b3);
            *(__half2*)(out + (size_t)nb_ * OUTF + c0)     = h01;
            *(__half2*)(out + (size_t)nb_ * OUTF + c0 + 2) = h23;
        }
    }
}

// ---------------------------------------------------------------------------
// CSR SpMM hop, fp16 gather / fp32 accumulate. 8 lanes per node, 8 cols each
// (one 16B LDG per edge per lane). OUT_HALF selects fp16 vs fp32 output.
// ---------------------------------------------------------------------------
template <bool OUT_HALF>
__global__ void spmm_csr_kernel(const int* __restrict__ row_ptr,
                                const int2* __restrict__ csr,
                                const __half* __restrict__ hin,
                                void* __restrict__ hout, int n)
{
    int t = blockIdx.x * blockDim.x + threadIdx.x;
    int v = t >> 3;
    if (v >= n) return;
    int q = (threadIdx.x & 7) * 8;   // column offset (halves)

    int beg = __ldg(&row_ptr[v]);
    int end = __ldg(&row_ptr[v + 1]);

    float a[8];
#pragma unroll
    for (int j = 0; j < 8; j++) a[j] = 0.f;

    int i = beg;
    for (; i + 2 <= end; i += 2) {
        int2 e0 = __ldg(&csr[i]);
        int2 e1 = __ldg(&csr[i + 1]);
        uint4 r0 = *(const uint4*)(hin + (size_t)e0.x * OUTF + q);
        uint4 r1 = *(const uint4*)(hin + (size_t)e1.x * OUTF + q);
        float w0 = __int_as_float(e0.y);
        float w1 = __int_as_float(e1.y);
        const unsigned* u0 = &r0.x;
        const unsigned* u1 = &r1.x;
#pragma unroll
        for (int j = 0; j < 4; j++) {
            float2 f0 = __half22float2(*(const __half2*)&u0[j]);
            float2 f1 = __half22float2(*(const __half2*)&u1[j]);
            a[2 * j + 0] = fmaf(w0, f0.x, a[2 * j + 0]);
            a[2 * j + 1] = fmaf(w0, f0.y, a[2 * j + 1]);
            a[2 * j + 0] = fmaf(w1, f1.x, a[2 * j + 0]);
            a[2 * j + 1] = fmaf(w1, f1.y, a[2 * j + 1]);
        }
    }
    if (i < end) {
        int2 e0 = __ldg(&csr[i]);
        uint4 r0 = *(const uint4*)(hin + (size_t)e0.x * OUTF + q);
        float w0 = __int_as_float(e0.y);
        const unsigned* u0 = &r0.x;
#pragma unroll
        for (int j = 0; j < 4; j++) {
            float2 f0 = __half22float2(*(const __half2*)&u0[j]);
            a[2 * j + 0] = fmaf(w0, f0.x, a[2 * j + 0]);
            a[2 * j + 1] = fmaf(w0, f0.y, a[2 * j + 1]);
        }
    }

    if (OUT_HALF) {
        __half* ho = (__half*)hout + (size_t)v * OUTF + q;
        uint4 o;
        unsigned* ou = &o.x;
#pragma unroll
        for (int j = 0; j < 4; j++) {
            __half2 h = __floats2half2_rn(a[2 * j], a[2 * j + 1]);
            ou[j] = *(const unsigned*)&h;
        }
        *(uint4*)ho = o;
    } else {
        float* fo = (float*)hout + (size_t)v * OUTF + q;
        float4 o0 = make_float4(a[0], a[1], a[2], a[3]);
        float4 o1 = make_float4(a[4], a[5], a[6], a[7]);
        *(float4*)(fo)     = o0;
        *(float4*)(fo + 4) = o1;
    }
}

// ---------------------------------------------------------------------------
extern "C" void kernel_launch(void* const* d_in, const int* in_sizes, int n_in,
                              void* d_out, int out_size)
{
    const float* x  = (const float*)d_in[0];
    const int*   ei = (const int*)d_in[1];
    const float* ew = (const float*)d_in[2];
    const float* Ww = (const float*)d_in[3];
    const float* Wb = (const float*)d_in[4];
    float* out = (float*)d_out;

    int n = in_sizes[0] / INF;     // 100000
    int E = in_sizes[2];           // 1600000

    __half *pA, *pB;
    int *pS, *pD, *pDeg, *pRow, *pW, *pBlk;
    int2 *pCsr;
    cudaGetSymbolAddress((void**)&pA, g_hA);
    cudaGetSymbolAddress((void**)&pB, g_hB);
    cudaGetSymbolAddress((void**)&pS, g_src);
    cudaGetSymbolAddress((void**)&pD, g_dst);
    cudaGetSymbolAddress((void**)&pDeg, g_deg);
    cudaGetSymbolAddress((void**)&pRow, g_row_ptr);
    cudaGetSymbolAddress((void**)&pW, g_wptr);
    cudaGetSymbolAddress((void**)&pBlk, g_blk);
    cudaGetSymbolAddress((void**)&pCsr, g_csr);

    const int GEMM_SMEM = 2 * INF * XT_STRIDE * (int)sizeof(float);  // 69632 B
    cudaFuncSetAttribute(gemm_kernel, cudaFuncAttributeMaxDynamicSharedMemorySize,
                         GEMM_SMEM);

    int nb = (n + 255) / 256;

    // ---- CSR build ----
    cudaMemsetAsync(pDeg, 0, (size_t)n * sizeof(int));
    extract_count_kernel<<<(E + 255) / 256, 256>>>(ei, E, pS, pD, pDeg);
    scan1_kernel<<<nb, 256>>>(pDeg, pBlk, n);
    scan2_kernel<<<1, 1024>>>(pBlk, nb);
    scan3_kernel<<<nb, 256>>>(pDeg, pBlk, pRow, pW, n, E);
    scatter_kernel<<<(E + 255) / 256, 256>>>(pS, pD, ew, pW, pCsr, E);

    // ---- h0 = fp16(x @ W^T + b) ----
    gemm_kernel<<<(n + 63) / 64, 256, GEMM_SMEM>>>(x, Ww, Wb, pA, n);

    // ---- 3 propagation hops (fp16 gather, fp32 accumulate) ----
    int hop_blocks = (n * 8 + 255) / 256;
    spmm_csr_kernel<true ><<<hop_blocks, 256>>>(pRow, pCsr, pA, pB, n);
    spmm_csr_kernel<true ><<<hop_blocks, 256>>>(pRow, pCsr, pB, pA, n);
    spmm_csr_kernel<false><<<hop_blocks, 256>>>(pRow, pCsr, pA, out, n);
}